// round 7
// baseline (speedup 1.0000x reference)
#include <cuda_runtime.h>
#include <stdint.h>

#define NPTS   8192
#define NWORDS 128            // NPTS/64 uint64 words per mask row
#define RAD2   64.0f          // radius^2 (radius = 8.0)
#define SPLIT  16             // j-split for rank counting
#define GRIDW  32             // 32x32 cells of 16px (512/16)
#define NCELLS (GRIDW*GRIDW)

typedef unsigned long long ull;

// ---- device scratch (no allocations allowed) ----
__device__ float g_sx[NPTS], g_sy[NPTS], g_ss[NPTS];
__device__ int   g_order[NPTS];
__device__ int   g_partial[SPLIT][NPTS];
__device__ __align__(16) ull g_mask[(size_t)NPTS * NWORDS];   // 8 MB, sparse
__device__ ull   g_diag[NPTS];          // diag word of each row, layout [chunk][b]
__device__ unsigned int g_nz32[NPTS / 32];  // per-chunk nonzero-diag ballot bits
__device__ int   g_cnt[NCELLS];
__device__ int   g_off[NCELLS];
__device__ int   g_fill[NCELLS];
__device__ int   g_cell_pts[NPTS];

__device__ __forceinline__ uint32_t f2mono(float f) {
    uint32_t b = __float_as_uint(f);
    return b ^ ((b & 0x80000000u) ? 0xFFFFFFFFu : 0x80000000u);
}
__device__ __forceinline__ int cell_of(float x, float y) {
    int cx = min(GRIDW - 1, (int)(x * 0.0625f));
    int cy = min(GRIDW - 1, (int)(y * 0.0625f));
    return cy * GRIDW + cx;
}

// ========== K1a: partial stable-descending ranks. grid (32,SPLIT) x 256 ==========
__global__ void rank_partial_kernel(const float* __restrict__ scores) {
    const int tid = threadIdx.x;
    const int i   = blockIdx.x * 256 + tid;
    const int by  = blockIdx.y;
    const uint32_t mi = f2mono(scores[i]);

    __shared__ uint32_t s_m[256];
    int cnt = 0;
    #pragma unroll
    for (int tile = 0; tile < (NPTS / SPLIT) / 256; ++tile) {
        const int j0 = by * (NPTS / SPLIT) + tile * 256;
        s_m[tid] = f2mono(scores[j0 + tid]);
        __syncthreads();
        #pragma unroll 16
        for (int jj = 0; jj < 256; ++jj) {
            const uint32_t mj = s_m[jj];
            const int j = j0 + jj;
            cnt += (mj > mi) || (mj == mi && j < i);
        }
        __syncthreads();
    }
    g_partial[by][i] = cnt;
}

// ========== K1b: combine ranks, scatter sorted arrays. grid 32 x 256 ==========
__global__ void rank_scatter_kernel(const float* __restrict__ coords,
                                    const float* __restrict__ scores) {
    const int i = blockIdx.x * 256 + threadIdx.x;
    int rank = 0;
    #pragma unroll
    for (int s = 0; s < SPLIT; ++s) rank += g_partial[s][i];
    g_order[rank] = i;
    g_ss[rank]    = scores[i];
    g_sx[rank]    = coords[2 * i + 0];
    g_sy[rank]    = coords[2 * i + 1];
}

// ========== K2a: zero mask (8MB) + cell counters. grid 2048 x 256 ==========
__global__ void zero_kernel() {
    const size_t idx = (size_t)blockIdx.x * 256 + threadIdx.x;   // 524288 threads
    ((ulonglong2*)g_mask)[idx] = make_ulonglong2(0ull, 0ull);
    if (idx < NCELLS) g_cnt[idx] = 0;
}

// ========== K2b: count points per cell. grid 32 x 256 ==========
__global__ void bin_count_kernel() {
    const int i = blockIdx.x * 256 + threadIdx.x;
    atomicAdd(&g_cnt[cell_of(g_sx[i], g_sy[i])], 1);
}

// ========== K2c: exclusive scan over 1024 cells. grid 1 x 1024 ==========
__global__ void scan_kernel() {
    __shared__ int s[NCELLS];
    const int t = threadIdx.x;
    const int my = g_cnt[t];
    s[t] = my;
    __syncthreads();
    for (int d = 1; d < NCELLS; d <<= 1) {
        int v = (t >= d) ? s[t - d] : 0;
        __syncthreads();
        s[t] += v;
        __syncthreads();
    }
    const int excl = s[t] - my;
    g_off[t]  = excl;
    g_fill[t] = excl;
}

// ========== K2d: fill cell point lists. grid 32 x 256 ==========
__global__ void bin_fill_kernel() {
    const int i = blockIdx.x * 256 + threadIdx.x;
    const int pos = atomicAdd(&g_fill[cell_of(g_sx[i], g_sy[i])], 1);
    g_cell_pts[pos] = i;        // sorted-rank index
}

// ========== K2e: close pairs via 3x3 cell neighborhood -> atomicOr bits.
// grid (32, 9) x 256: blockIdx.y selects the neighbor cell offset. ==========
__global__ void pair_kernel() {
    const int i  = blockIdx.x * 256 + threadIdx.x;
    const int by = blockIdx.y;
    const float xi = g_sx[i], yi = g_sy[i];
    const int cx = min(GRIDW - 1, (int)(xi * 0.0625f));
    const int cy = min(GRIDW - 1, (int)(yi * 0.0625f));
    const int xx = cx + (by % 3) - 1;
    const int yy = cy + (by / 3) - 1;
    if (xx < 0 || xx >= GRIDW || yy < 0 || yy >= GRIDW) return;
    const int cell = yy * GRIDW + xx;
    const int off = g_off[cell];
    const int cnt = g_cnt[cell];
    for (int k = 0; k < cnt; ++k) {
        const int j = g_cell_pts[off + k];
        if (j > i) {
            const float dx = xi - g_sx[j];
            const float dy = yi - g_sy[j];
            const float d2 = dx * dx + dy * dy;   // same fp expr as R3-passing kernel
            if (d2 < RAD2)
                atomicOr(&g_mask[(size_t)i * NWORDS + (j >> 6)], 1ull << (j & 63));
        }
    }
}

// ========== K2f: compact diag words + nonzero ballot. grid 32 x 256 ==========
__global__ void diag_kernel() {
    const int i = blockIdx.x * 256 + threadIdx.x;
    const ull w = g_mask[(size_t)i * NWORDS + (i >> 6)];
    g_diag[i] = w;
    const unsigned bal = __ballot_sync(0xFFFFFFFFu, w != 0ull);
    if ((i & 31) == 0) g_nz32[i >> 5] = bal;
}

// ========== K3: sequential greedy sweep + output. 1 block x 128 threads.
// Diag columns live in shared (loaded once). Serial chain visits only
// nonzero-diag kept bits (~1-2/chunk). OR phase loads only kept rows' words. ==========
__global__ void __launch_bounds__(128, 1)
sweep_kernel(float* __restrict__ out, int out_size) {
    extern __shared__ ull s_diag[];        // NPTS words = 64 KB
    __shared__ ull s_kb;
    __shared__ ull s_remv[NWORDS];

    const int t = threadIdx.x;
    for (int idx = t; idx < NPTS; idx += 128) s_diag[idx] = g_diag[idx];
    const ull nz = ((ull)g_nz32[2 * t + 1] << 32) | (ull)g_nz32[2 * t];
    ull remv = 0ull;
    __syncthreads();

    for (int c = 0; c < NWORDS; ++c) {
        if (t == c) {
            ull rem = remv, done = 0ull;
            ull cand = nz & ~rem;
            while (cand) {
                const int b = __ffsll(cand) - 1;   // lowest kept bit w/ nonzero diag
                done |= 1ull << b;
                rem  |= s_diag[(c << 6) + b];      // diag word has only bits > b
                cand  = nz & ~rem & ~done;
            }
            remv = rem;
            s_kb = ~rem;                           // kept bits of this chunk
        }
        __syncthreads();

        if (t > c) {
            ull k = s_kb;
            const ull* rowbase = g_mask + ((size_t)(c << 6)) * NWORDS + t;
            while (k) {
                const int b = __ffsll(k) - 1;
                k &= k - 1;
                remv |= rowbase[(size_t)b * NWORDS];
            }
        }
        __syncthreads();                           // protect s_kb
    }

    s_remv[t] = remv;
    __syncthreads();

    for (int i = t; i < NPTS; i += 128) {
        const bool kept = !((s_remv[i >> 6] >> (i & 63)) & 1ull);
        const int  o    = g_order[i];
        if (out_size >= 2 * NPTS) {
            out[o]        = kept ? 1.0f : 0.0f;
            out[NPTS + i] = kept ? g_ss[i] : 0.0f;
        } else {
            out[o] = kept ? 1.0f : 0.0f;
        }
    }
}

extern "C" void kernel_launch(void* const* d_in, const int* in_sizes, int n_in,
                              void* d_out, int out_size) {
    const float* coords = (const float*)d_in[0];  // [N,2] f32
    const float* scores = (const float*)d_in[1];  // [N]   f32
    float* out = (float*)d_out;

    cudaFuncSetAttribute(sweep_kernel,
                         cudaFuncAttributeMaxDynamicSharedMemorySize,
                         NPTS * (int)sizeof(ull));

    dim3 rg(NPTS / 256, SPLIT);
    rank_partial_kernel<<<rg, 256>>>(scores);
    rank_scatter_kernel<<<NPTS / 256, 256>>>(coords, scores);

    zero_kernel<<<(NPTS * NWORDS / 2) / 256, 256>>>();
    bin_count_kernel<<<NPTS / 256, 256>>>();
    scan_kernel<<<1, NCELLS>>>();
    bin_fill_kernel<<<NPTS / 256, 256>>>();
    pair_kernel<<<dim3(NPTS / 256, 9), 256>>>();
    diag_kernel<<<NPTS / 256, 256>>>();

    sweep_kernel<<<1, 128, NPTS * sizeof(ull)>>>(out, out_size);
}

// round 8
// speedup vs baseline: 3.4489x; 3.4489x over previous
#include <cuda_runtime.h>
#include <stdint.h>

#define NPTS   8192
#define NWORDS 128            // NPTS/64 keep-mask words
#define RAD2   64.0f          // radius^2 (radius = 8.0)
#define SPLIT  16             // j-split for rank counting
#define GRIDW  32             // 32x32 cells of 16px (512/16)
#define NCELLS (GRIDW*GRIDW)
#define MAXDEG 16             // cross-chunk forward neighbors per row (avg ~3)

typedef unsigned long long ull;

// ---- device scratch (no allocations allowed) ----
__device__ float g_sx[NPTS], g_sy[NPTS], g_ss[NPTS];
__device__ int   g_order[NPTS];
__device__ int   g_partial[SPLIT][NPTS];
__device__ ull   g_diag[NPTS];                       // intra-chunk suppression word per row
__device__ int   g_adj_cnt[NPTS];                    // cross-chunk forward degree
__device__ __align__(16) uint16_t g_adj[NPTS * MAXDEG];  // neighbor j (sorted index), 256 KB
__device__ int   g_cnt[NCELLS];
__device__ int   g_off[NCELLS];
__device__ int   g_fill[NCELLS];
__device__ int   g_cell_pts[NPTS];

__device__ __forceinline__ uint32_t f2mono(float f) {
    uint32_t b = __float_as_uint(f);
    return b ^ ((b & 0x80000000u) ? 0xFFFFFFFFu : 0x80000000u);
}
__device__ __forceinline__ int cell_of(float x, float y) {
    int cx = min(GRIDW - 1, (int)(x * 0.0625f));
    int cy = min(GRIDW - 1, (int)(y * 0.0625f));
    return cy * GRIDW + cx;
}

// ========== K1: partial stable-descending ranks + scratch zeroing.
// grid (32, SPLIT) x 256 ==========
__global__ void rank_partial_kernel(const float* __restrict__ scores) {
    const int tid = threadIdx.x;
    const int i   = blockIdx.x * 256 + tid;
    const int by  = blockIdx.y;

    // fold scratch zeroing into this (first) kernel
    const int gid = (blockIdx.y * gridDim.x + blockIdx.x) * 256 + tid;
    if (gid < NPTS) { g_diag[gid] = 0ull; g_adj_cnt[gid] = 0; }
    if (gid >= NPTS && gid < NPTS + NCELLS) g_cnt[gid - NPTS] = 0;

    const uint32_t mi = f2mono(scores[i]);
    __shared__ uint32_t s_m[256];
    int cnt = 0;
    #pragma unroll
    for (int tile = 0; tile < (NPTS / SPLIT) / 256; ++tile) {
        const int j0 = by * (NPTS / SPLIT) + tile * 256;
        s_m[tid] = f2mono(scores[j0 + tid]);
        __syncthreads();
        #pragma unroll 16
        for (int jj = 0; jj < 256; ++jj) {
            const uint32_t mj = s_m[jj];
            const int j = j0 + jj;
            cnt += (mj > mi) || (mj == mi && j < i);
        }
        __syncthreads();
    }
    g_partial[by][i] = cnt;
}

// ========== K2: combine ranks, scatter sorted arrays, count cells.
// Cell counts use ORIGINAL coords (permutation-invariant). grid 32 x 256 ==========
__global__ void rank_scatter_kernel(const float* __restrict__ coords,
                                    const float* __restrict__ scores) {
    const int i = blockIdx.x * 256 + threadIdx.x;
    int rank = 0;
    #pragma unroll
    for (int s = 0; s < SPLIT; ++s) rank += g_partial[s][i];
    const float x = coords[2 * i + 0];
    const float y = coords[2 * i + 1];
    g_order[rank] = i;
    g_ss[rank]    = scores[i];
    g_sx[rank]    = x;
    g_sy[rank]    = y;
    atomicAdd(&g_cnt[cell_of(x, y)], 1);
}

// ========== K3: exclusive scan over 1024 cells. grid 1 x 1024 ==========
__global__ void scan_kernel() {
    __shared__ int s[NCELLS];
    const int t = threadIdx.x;
    const int my = g_cnt[t];
    s[t] = my;
    __syncthreads();
    for (int d = 1; d < NCELLS; d <<= 1) {
        int v = (t >= d) ? s[t - d] : 0;
        __syncthreads();
        s[t] += v;
        __syncthreads();
    }
    const int excl = s[t] - my;
    g_off[t]  = excl;
    g_fill[t] = excl;
}

// ========== K4: fill cell point lists (sorted indices). grid 32 x 256 ==========
__global__ void bin_fill_kernel() {
    const int i = blockIdx.x * 256 + threadIdx.x;
    const int pos = atomicAdd(&g_fill[cell_of(g_sx[i], g_sy[i])], 1);
    g_cell_pts[pos] = i;
}

// ========== K5: close pairs via 3x3 neighborhood -> diag bits + adjacency lists.
// grid (32, 9) x 256 ==========
__global__ void pair_kernel() {
    const int i  = blockIdx.x * 256 + threadIdx.x;
    const int by = blockIdx.y;
    const float xi = g_sx[i], yi = g_sy[i];
    const int cx = min(GRIDW - 1, (int)(xi * 0.0625f));
    const int cy = min(GRIDW - 1, (int)(yi * 0.0625f));
    const int xx = cx + (by % 3) - 1;
    const int yy = cy + (by / 3) - 1;
    if (xx < 0 || xx >= GRIDW || yy < 0 || yy >= GRIDW) return;
    const int cell = yy * GRIDW + xx;
    const int off = g_off[cell];
    const int cnt = g_cnt[cell];
    for (int k = 0; k < cnt; ++k) {
        const int j = g_cell_pts[off + k];
        if (j > i) {
            const float dx = xi - g_sx[j];
            const float dy = yi - g_sy[j];
            const float d2 = dx * dx + dy * dy;     // identical fp expr to passing rounds
            if (d2 < RAD2) {
                if ((j >> 6) == (i >> 6)) {
                    atomicOr(&g_diag[i], 1ull << (j & 63));
                } else {
                    const int slot = atomicAdd(&g_adj_cnt[i], 1);
                    if (slot < MAXDEG)
                        g_adj[i * MAXDEG + slot] = (uint16_t)j;
                }
            }
        }
    }
}

// ========== K6: sequential greedy sweep + output. 1 block x 128 threads.
// Shared: diag words (64KB), degrees (8KB), per-chunk nz ballots (1KB).
// Per chunk: prefetch chunk adjacency (1 LDG.128/thread, hidden behind
// serial phase), serial intra-chunk chain, parallel smem atomicOr of
// kept rows' cross-chunk neighbors. ==========
__global__ void __launch_bounds__(128, 1)
sweep_kernel(float* __restrict__ out, int out_size) {
    extern __shared__ char smem[];
    ull*     s_diag = (ull*)smem;                        // [NPTS]     64 KB
    uint8_t* s_cnt  = (uint8_t*)(s_diag + NPTS);         // [NPTS]      8 KB
    ull*     s_nz   = (ull*)(s_cnt + NPTS);              // [NWORDS]    1 KB
    __shared__ ull s_remv[NWORDS];
    __shared__ ull s_kb;

    const int t    = threadIdx.x;
    const int b    = t & 63;      // row-within-chunk this thread owns
    const int half = t >> 6;      // which 8-entry half of the adjacency row

    for (int idx = t; idx < NPTS; idx += 128) {
        s_diag[idx] = g_diag[idx];
        s_cnt[idx]  = (uint8_t)min(g_adj_cnt[idx], MAXDEG);
    }
    s_remv[t] = 0ull;
    __syncthreads();

    {   // per-chunk nonzero-diag ballots
        ull nz = 0ull;
        #pragma unroll 8
        for (int bb = 0; bb < 64; ++bb)
            if (s_diag[(t << 6) + bb] != 0ull) nz |= 1ull << bb;
        s_nz[t] = nz;
    }
    __syncthreads();

    for (int c = 0; c < NWORDS; ++c) {
        const int row = (c << 6) + b;

        // prefetch this chunk's adjacency entries (independent LDG.128;
        // completes during the serial phase + barrier)
        const ulonglong2 ev =
            *(const ulonglong2*)&g_adj[(size_t)row * MAXDEG + (half << 3)];

        if (t == c) {
            ull r = s_remv[c], done = 0ull;
            ull cand = s_nz[c] & ~r;
            while (cand) {
                const int bit = __ffsll(cand) - 1;
                done |= 1ull << bit;
                r    |= s_diag[(c << 6) + bit];   // only bits > bit set
                cand  = s_nz[c] & ~r & ~done;
            }
            s_remv[c] = r;
            s_kb = ~r;                            // kept rows of this chunk
        }
        __syncthreads();

        if ((s_kb >> b) & 1ull) {
            const int n = (int)s_cnt[row] - (half << 3);
            if (n > 0) {
                #pragma unroll
                for (int k = 0; k < 8; ++k) {
                    if (k < n) {
                        const int j = (int)((k < 4 ? (ev.x >> (k * 16))
                                                   : (ev.y >> ((k - 4) * 16))) & 0xFFFFu);
                        atomicOr(&s_remv[j >> 6], 1ull << (j & 63));
                    }
                }
            }
        }
        __syncthreads();
    }

    // outputs: [keep_orig (0/1 float, original order), suppressed_scores (sorted order)]
    for (int i = t; i < NPTS; i += 128) {
        const bool kept = !((s_remv[i >> 6] >> (i & 63)) & 1ull);
        const int  o    = g_order[i];
        if (out_size >= 2 * NPTS) {
            out[o]        = kept ? 1.0f : 0.0f;
            out[NPTS + i] = kept ? g_ss[i] : 0.0f;
        } else {
            out[o] = kept ? 1.0f : 0.0f;
        }
    }
}

extern "C" void kernel_launch(void* const* d_in, const int* in_sizes, int n_in,
                              void* d_out, int out_size) {
    const float* coords = (const float*)d_in[0];  // [N,2] f32
    const float* scores = (const float*)d_in[1];  // [N]   f32
    float* out = (float*)d_out;

    const int sweep_smem = NPTS * (int)sizeof(ull) + NPTS + NWORDS * (int)sizeof(ull);
    cudaFuncSetAttribute(sweep_kernel,
                         cudaFuncAttributeMaxDynamicSharedMemorySize, sweep_smem);

    dim3 rg(NPTS / 256, SPLIT);
    rank_partial_kernel<<<rg, 256>>>(scores);
    rank_scatter_kernel<<<NPTS / 256, 256>>>(coords, scores);
    scan_kernel<<<1, NCELLS>>>();
    bin_fill_kernel<<<NPTS / 256, 256>>>();
    pair_kernel<<<dim3(NPTS / 256, 9), 256>>>();
    sweep_kernel<<<1, 128, sweep_smem>>>(out, out_size);
}